// round 1
// baseline (speedup 1.0000x reference)
#include <cuda_runtime.h>

// Problem constants (fixed shapes from setup_inputs)
#define BB 4
#define CC 19
#define HH 256
#define WW 256
#define HW (HH * WW)
#define CHW (CC * HW)
#define RAD 10

// Scratch (device globals; no allocation allowed)
__device__ float g_ent[BB * HW];
__device__ float g_kl[BB * HW];
__device__ unsigned char g_fg[BB * HW];
__device__ unsigned char g_v[BB * HW];
__device__ int g_entmax[BB];      // entropy >= 0, so int-reinterpreted atomicMax is order-preserving
__device__ double g_sum_wkl;
__device__ double g_sum_w;

__global__ void k0_init() {
    int t = threadIdx.x;
    if (t < BB) g_entmax[t] = 0;
    if (t == 0) { g_sum_wkl = 0.0; g_sum_w = 0.0; }
}

// K1: one thread per pixel. Reads teacher+student (all 19 channels each),
// computes fg (argmax != 0), teacher entropy, per-pixel KL. Block-reduces
// entropy max -> atomicMax per image.
__global__ void __launch_bounds__(256) k1_channelwise(
    const float* __restrict__ student, const float* __restrict__ teacher)
{
    const int b = blockIdx.y;
    const int p = blockIdx.x * blockDim.x + threadIdx.x;  // pixel in [0, HW)
    const float* tb = teacher + (size_t)b * CHW + p;
    const float* sb = student + (size_t)b * CHW + p;

    float tl[CC], sl[CC];
#pragma unroll
    for (int c = 0; c < CC; c++) tl[c] = __ldg(tb + c * HW) * 0.25f;  // /TEMP
#pragma unroll
    for (int c = 0; c < CC; c++) sl[c] = __ldg(sb + c * HW) * 0.25f;

    // fg = argmax(teacher) != 0  <=>  max_{c>=1} > chan0 (strict; ties pick index 0)
    float mfg = tl[1];
#pragma unroll
    for (int c = 2; c < CC; c++) mfg = fmaxf(mfg, tl[c]);
    const bool fg = (mfg > tl[0]);
    const float m = fmaxf(mfg, tl[0]);

    // teacher softmax stats: Z = sum exp(lt-m), S = sum lt*exp(lt-m)
    float Z = 0.f, S = 0.f;
#pragma unroll
    for (int c = 0; c < CC; c++) {
        float e = __expf(tl[c] - m);
        Z += e;
        S += tl[c] * e;
    }
    const float tlse = m + __logf(Z);        // log-sum-exp of teacher/T
    const float Hent = tlse - S / Z;         // entropy = -sum p log p

    // student log-sum-exp
    float ms = sl[0];
#pragma unroll
    for (int c = 1; c < CC; c++) ms = fmaxf(ms, sl[c]);
    float Zs = 0.f;
#pragma unroll
    for (int c = 0; c < CC; c++) Zs += __expf(sl[c] - ms);
    const float slse = ms + __logf(Zs);

    // KL = sum_c p_c * (log p_c - slogp_c)
    float kl = 0.f;
#pragma unroll
    for (int c = 0; c < CC; c++) {
        float lp = tl[c] - tlse;             // log p_c
        kl += __expf(lp) * (lp - (sl[c] - slse));
    }

    const int idx = b * HW + p;
    g_ent[idx] = Hent;
    g_kl[idx] = kl;
    g_fg[idx] = fg ? 1 : 0;

    // block max of entropy -> atomicMax per image
    __shared__ float smax[256];
    smax[threadIdx.x] = Hent;
    __syncthreads();
#pragma unroll
    for (int o = 128; o > 0; o >>= 1) {
        if (threadIdx.x < o)
            smax[threadIdx.x] = fmaxf(smax[threadIdx.x], smax[threadIdx.x + o]);
        __syncthreads();
    }
    if (threadIdx.x == 0) atomicMax(&g_entmax[b], __float_as_int(smax[0]));
}

// K2: vertical pass of bounded EDT: v[i][j] = min di^2 over fg within |di|<=10 (else 200)
__global__ void __launch_bounds__(256) k2_vertical()
{
    const int idx = blockIdx.x * blockDim.x + threadIdx.x;  // over B*HW
    const int b = idx >> 16;          // /HW (HW=65536)
    const int p = idx & (HW - 1);
    const int i = p >> 8;             // /WW
    const int j = p & (WW - 1);
    int v = 200;
#pragma unroll
    for (int di = -RAD; di <= RAD; di++) {
        int ii = i + di;
        if (ii >= 0 && ii < HH) {
            if (g_fg[b * HW + ii * WW + j]) v = min(v, di * di);
        }
    }
    g_v[idx] = (unsigned char)v;
}

// K3: horizontal pass -> dist2; gaussian weight * boundary bonus * confidence;
// accumulate sum(w*kl) and sum(w).
__global__ void __launch_bounds__(256) k3_weights()
{
    const int b = blockIdx.y;
    const int p = blockIdx.x * blockDim.x + threadIdx.x;
    const int i = p >> 8;
    const int j = p & (WW - 1);
    const int idx = b * HW + p;
    const int rowbase = b * HW + i * WW;

    int d2 = 300;
#pragma unroll
    for (int dj = -RAD; dj <= RAD; dj++) {
        int jj = j + dj;
        if (jj >= 0 && jj < WW) {
            d2 = min(d2, dj * dj + (int)g_v[rowbase + jj]);
        }
    }

    float w = 0.f;
    if (d2 <= RAD * RAD) {
        float wd = __expf(-(float)d2 * (1.0f / 50.0f));  // sigma = R/2 -> 2*sigma^2 = 50
        float bnd = 0.f;
        if (g_fg[idx]) {
            bool er = true;  // 4-connected erosion, OOB = background
            er = er && (i > 0)      && (g_fg[idx - WW] != 0);
            er = er && (i < HH - 1) && (g_fg[idx + WW] != 0);
            er = er && (j > 0)      && (g_fg[idx - 1] != 0);
            er = er && (j < WW - 1) && (g_fg[idx + 1] != 0);
            if (!er) bnd = 1.f;
        }
        float Hm = __int_as_float(g_entmax[b]);
        float conf = 0.1f + 0.9f * (1.f - g_ent[idx] / (Hm + 1e-8f));
        w = wd * (1.f + bnd) * conf;  // mask applied once (binary: mask^2 == mask)
    }

    float c1 = w * g_kl[idx];
    float c2 = w;

    // block reduction of (c1, c2)
    __shared__ float s1[256], s2[256];
    s1[threadIdx.x] = c1;
    s2[threadIdx.x] = c2;
    __syncthreads();
#pragma unroll
    for (int o = 128; o > 0; o >>= 1) {
        if (threadIdx.x < o) {
            s1[threadIdx.x] += s1[threadIdx.x + o];
            s2[threadIdx.x] += s2[threadIdx.x + o];
        }
        __syncthreads();
    }
    if (threadIdx.x == 0) {
        atomicAdd(&g_sum_wkl, (double)s1[0]);
        atomicAdd(&g_sum_w, (double)s2[0]);
    }
}

__global__ void k4_finalize(float* __restrict__ out)
{
    out[0] = (float)(16.0 * g_sum_wkl / (g_sum_w + 1e-8));
}

extern "C" void kernel_launch(void* const* d_in, const int* in_sizes, int n_in,
                              void* d_out, int out_size)
{
    const float* student = (const float*)d_in[0];
    const float* teacher = (const float*)d_in[1];
    float* out = (float*)d_out;

    dim3 gridPix(HW / 256, BB);

    k0_init<<<1, 32>>>();
    k1_channelwise<<<gridPix, 256>>>(student, teacher);
    k2_vertical<<<(BB * HW) / 256, 256>>>();
    k3_weights<<<gridPix, 256>>>();
    k4_finalize<<<1, 1>>>(out);
}

// round 2
// speedup vs baseline: 1.0122x; 1.0122x over previous
#include <cuda_runtime.h>

// Fixed problem shape
#define BB 4
#define CC 19
#define HH 256
#define WW 256
#define HW (HH * WW)
#define CHW (CC * HW)
#define RAD 10
#define TS 32            // tile size for fused EDT/weight kernel
#define EW (TS + 2*RAD)  // 52: tile + halo

// Scratch (device globals; no allocation allowed)
__device__ float g_ent[BB * HW];
__device__ float g_kl[BB * HW];
__device__ unsigned char g_fg[BB * HW];
__device__ int g_entmax[BB];   // entropy > 0 -> int-reinterpreted atomicMax is order-preserving
__device__ double g_sum_wkl;
__device__ double g_sum_w;

__global__ void k0_init() {
    int t = threadIdx.x;
    if (t < BB) g_entmax[t] = 0;
    if (t == 0) { g_sum_wkl = 0.0; g_sum_w = 0.0; }
}

// ---------------------------------------------------------------------------
// K1: 4 pixels/thread via float4. Single pass over channels, no max-subtract
// (logits ~ N(0,1)/4 -> exp is safe), no register arrays:
//   Z  = sum exp(t_c), S = sum exp(t_c)*t_c, T = sum exp(t_c)*s_c, Zs = sum exp(s_c)
//   ent = logZ - S/Z
//   kl  = (S - T)/Z - logZ + logZs
// ---------------------------------------------------------------------------
__global__ void __launch_bounds__(256) k1_channelwise(
    const float* __restrict__ student, const float* __restrict__ teacher)
{
    const int b = blockIdx.y;
    const int p = (blockIdx.x * blockDim.x + threadIdx.x) * 4;
    const size_t base = (size_t)b * CHW + p;

    float Z[4]  = {0,0,0,0};
    float S[4]  = {0,0,0,0};
    float Tt[4] = {0,0,0,0};
    float Zs[4] = {0,0,0,0};
    float t0[4], mx[4];

#pragma unroll
    for (int c = 0; c < CC; c++) {
        float4 t4 = *(const float4*)(teacher + base + (size_t)c * HW);
        float4 s4 = *(const float4*)(student + base + (size_t)c * HW);
        float tv[4] = {t4.x*0.25f, t4.y*0.25f, t4.z*0.25f, t4.w*0.25f};
        float sv[4] = {s4.x*0.25f, s4.y*0.25f, s4.z*0.25f, s4.w*0.25f};
#pragma unroll
        for (int l = 0; l < 4; l++) {
            float e = __expf(tv[l]);
            Z[l]  += e;
            S[l]  += e * tv[l];
            Tt[l] += e * sv[l];
            Zs[l] += __expf(sv[l]);
            if (c == 0) { t0[l] = tv[l]; mx[l] = -1e30f; }
            else        { mx[l] = fmaxf(mx[l], tv[l]); }
        }
    }

    float ent[4], kl[4];
    unsigned char fg[4];
    float entm = -1e30f;
#pragma unroll
    for (int l = 0; l < 4; l++) {
        float lZ  = __logf(Z[l]);
        float lZs = __logf(Zs[l]);
        ent[l] = lZ - S[l] / Z[l];
        kl[l]  = (S[l] - Tt[l]) / Z[l] - lZ + lZs;
        fg[l]  = (mx[l] > t0[l]) ? 1 : 0;
        entm = fmaxf(entm, ent[l]);
    }

    const int idx = b * HW + p;
    *(float4*)(g_ent + idx) = make_float4(ent[0], ent[1], ent[2], ent[3]);
    *(float4*)(g_kl  + idx) = make_float4(kl[0],  kl[1],  kl[2],  kl[3]);
    *(uchar4*)(g_fg  + idx) = make_uchar4(fg[0], fg[1], fg[2], fg[3]);

    // warp-shuffle max, then one smem stage, then atomicMax per image
#pragma unroll
    for (int o = 16; o > 0; o >>= 1)
        entm = fmaxf(entm, __shfl_xor_sync(0xFFFFFFFF, entm, o));
    __shared__ float smax[8];
    if ((threadIdx.x & 31) == 0) smax[threadIdx.x >> 5] = entm;
    __syncthreads();
    if (threadIdx.x == 0) {
        float m = smax[0];
#pragma unroll
        for (int w = 1; w < 8; w++) m = fmaxf(m, smax[w]);
        atomicMax(&g_entmax[b], __float_as_int(m));
    }
}

// ---------------------------------------------------------------------------
// K2: fused bounded-EDT (vertical + horizontal) + boundary + confidence +
// weighted accumulation, all taps in shared memory. One 32x32 tile per block.
// Vertical pass is 4-columns-at-a-time byte SIMD: term = 200 - fg*(200-d^2)
// (carry-free: every byte value <= 200).
// ---------------------------------------------------------------------------
__global__ void __launch_bounds__(256) k2_edt_weights()
{
    const int b  = blockIdx.z;
    const int i0 = blockIdx.y * TS;
    const int j0 = blockIdx.x * TS;
    const int tid = threadIdx.x;

    __shared__ unsigned char sfg[EW][56];   // 52x52 halo, row stride 56 (u32-aligned)
    __shared__ unsigned char sv[TS][56];    // vertical min-d^2 per (row, halo-col)

    // Load fg halo (OOB -> 0, which matches border_value=0 semantics)
    for (int t = tid; t < EW * 56; t += 256) {
        int r = t / 56, c = t % 56;
        unsigned char f = 0;
        if (c < EW) {
            int gi = i0 - RAD + r, gj = j0 - RAD + c;
            if (gi >= 0 && gi < HH && gj >= 0 && gj < WW)
                f = g_fg[b * HW + gi * WW + gj];
        }
        sfg[r][c] = f;
    }
    __syncthreads();

    // Vertical pass: v[r][c] = min over |dr|<=10 of (fg ? dr^2 : 200)
    // 32 rows x 13 u32-words (52 cols)
    for (int t = tid; t < TS * 13; t += 256) {
        int r = t / 13, wc = (t % 13) * 4;
        unsigned int v4 = 0xC8C8C8C8u;   // 200 per byte
#pragma unroll
        for (int dr = 0; dr < 21; dr++) {
            unsigned int f4 = *(const unsigned int*)&sfg[r + dr][wc];
            int d = dr - RAD;
            unsigned int term = 0xC8C8C8C8u - f4 * (unsigned int)(200 - d * d);
            v4 = __vminu4(v4, term);
        }
        *(unsigned int*)&sv[r][wc] = v4;
    }
    __syncthreads();

    // Horizontal pass + weights, 4 pixels/thread (rows ty, ty+8, ty+16, ty+24)
    const int tx = tid & 31;
    const int ty = tid >> 5;
    const float Hm = __int_as_float(g_entmax[b]);
    const float invHm = 1.0f / (Hm + 1e-8f);

    float a_wkl = 0.f, a_w = 0.f;
#pragma unroll
    for (int k = 0; k < 4; k++) {
        int r = ty + 8 * k;
        int d2 = 300;
#pragma unroll
        for (int dj = 0; dj < 21; dj++) {
            int dd = dj - RAD;
            d2 = min(d2, dd * dd + (int)sv[r][tx + dj]);
        }
        if (d2 <= RAD * RAD) {
            float wd = __expf((float)d2 * (-1.0f / 50.0f));  // 2*sigma^2 = 50
            float bnd = 0.f;
            if (sfg[r + RAD][tx + RAD]) {
                bool er = sfg[r + RAD - 1][tx + RAD] && sfg[r + RAD + 1][tx + RAD]
                       && sfg[r + RAD][tx + RAD - 1] && sfg[r + RAD][tx + RAD + 1];
                if (!er) bnd = 1.f;
            }
            const int idx = b * HW + (i0 + r) * WW + (j0 + tx);
            float conf = 0.1f + 0.9f * (1.f - g_ent[idx] * invHm);
            float w = wd * (1.f + bnd) * conf;
            a_wkl += w * g_kl[idx];
            a_w   += w;
        }
    }

    // warp shuffle reduce -> smem -> block atomics
#pragma unroll
    for (int o = 16; o > 0; o >>= 1) {
        a_wkl += __shfl_xor_sync(0xFFFFFFFF, a_wkl, o);
        a_w   += __shfl_xor_sync(0xFFFFFFFF, a_w, o);
    }
    __shared__ float r1[8], r2[8];
    if ((tid & 31) == 0) { r1[tid >> 5] = a_wkl; r2[tid >> 5] = a_w; }
    __syncthreads();
    if (tid == 0) {
        float s1 = 0.f, s2 = 0.f;
#pragma unroll
        for (int w = 0; w < 8; w++) { s1 += r1[w]; s2 += r2[w]; }
        atomicAdd(&g_sum_wkl, (double)s1);
        atomicAdd(&g_sum_w, (double)s2);
    }
}

__global__ void k3_finalize(float* __restrict__ out)
{
    out[0] = (float)(16.0 * g_sum_wkl / (g_sum_w + 1e-8));
}

extern "C" void kernel_launch(void* const* d_in, const int* in_sizes, int n_in,
                              void* d_out, int out_size)
{
    const float* student = (const float*)d_in[0];
    const float* teacher = (const float*)d_in[1];
    float* out = (float*)d_out;

    k0_init<<<1, 32>>>();
    k1_channelwise<<<dim3(HW / 1024, BB), 256>>>(student, teacher);
    k2_edt_weights<<<dim3(HH / TS, WW / TS, BB), 256>>>();
    k3_finalize<<<1, 1>>>(out);
}

// round 3
// speedup vs baseline: 1.1085x; 1.0952x over previous
#include <cuda_runtime.h>

// Fixed problem shape
#define BB 4
#define CC 19
#define HH 256
#define WW 256
#define HW (HH * WW)
#define CHW (CC * HW)
#define RAD 10
#define TS 32
#define EW (TS + 2 * RAD)   // 52
#define NBLK 256            // total blocks (must all be co-resident)

// Scratch (device globals; zero-initialized at load, reset at end of each run)
__device__ unsigned char g_fg[BB * HW];
__device__ int g_entmax[BB];        // entropy > 0 -> int atomicMax is order-preserving
__device__ double g_sum_wkl;
__device__ double g_sum_w;
__device__ unsigned int g_arr;      // barrier arrive
__device__ unsigned int g_dep;      // barrier depart
__device__ unsigned int g_done;     // completion counter for finalize election

__global__ void __launch_bounds__(256, 2) ofkd_fused(
    const float* __restrict__ student, const float* __restrict__ teacher,
    float* __restrict__ out)
{
    const int b  = blockIdx.y;
    const int ti = blockIdx.x >> 3;
    const int tj = blockIdx.x & 7;
    const int i0 = ti * TS, j0 = tj * TS;
    const int tid = threadIdx.x;
    const int ty  = tid >> 3;          // tile row 0..31
    const int tx0 = (tid & 7) * 4;     // tile col base (4 consecutive px/thread)

    // ======== Phase A: channel-wise math for this block's own 32x32 tile ====
    // Single pass, no max-subtract (logits/4 are small):
    //   Z = sum e^t, S = sum t e^t, T = sum s e^t, Zs = sum e^s
    //   ent = logZ - S/Z ;  kl = (S-T)/Z - logZ + logZs
    const size_t base = (size_t)b * CHW + (size_t)(i0 + ty) * WW + j0 + tx0;
    float Z[4] = {0,0,0,0}, S[4] = {0,0,0,0}, Tt[4] = {0,0,0,0}, Zs[4] = {0,0,0,0};
    float t0[4], mx[4];

#pragma unroll
    for (int c = 0; c < CC; c++) {
        float4 t4 = *(const float4*)(teacher + base + (size_t)c * HW);
        float4 s4 = *(const float4*)(student + base + (size_t)c * HW);
        float tv[4] = {t4.x*0.25f, t4.y*0.25f, t4.z*0.25f, t4.w*0.25f};
        float sv_[4] = {s4.x*0.25f, s4.y*0.25f, s4.z*0.25f, s4.w*0.25f};
#pragma unroll
        for (int l = 0; l < 4; l++) {
            float e = __expf(tv[l]);
            Z[l]  += e;
            S[l]  += e * tv[l];
            Tt[l] += e * sv_[l];
            Zs[l] += __expf(sv_[l]);
            if (c == 0) { t0[l] = tv[l]; mx[l] = -1e30f; }
            else        { mx[l] = fmaxf(mx[l], tv[l]); }
        }
    }

    float ent[4], kl[4];
    unsigned char fgb[4];
    float entm = -1e30f;
#pragma unroll
    for (int l = 0; l < 4; l++) {
        float lZ = __logf(Z[l]), lZs = __logf(Zs[l]);
        ent[l] = lZ - S[l] / Z[l];
        kl[l]  = (S[l] - Tt[l]) / Z[l] - lZ + lZs;
        fgb[l] = (mx[l] > t0[l]) ? 1 : 0;    // argmax != 0 (ties -> class 0)
        entm = fmaxf(entm, ent[l]);
    }
    *(uchar4*)(g_fg + b * HW + (i0 + ty) * WW + j0 + tx0) =
        make_uchar4(fgb[0], fgb[1], fgb[2], fgb[3]);

    // per-image entropy max
#pragma unroll
    for (int o = 16; o > 0; o >>= 1)
        entm = fmaxf(entm, __shfl_xor_sync(0xFFFFFFFF, entm, o));
    __shared__ float smax[8];
    if ((tid & 31) == 0) smax[tid >> 5] = entm;
    __syncthreads();
    if (tid == 0) {
        float m = smax[0];
#pragma unroll
        for (int w = 1; w < 8; w++) m = fmaxf(m, smax[w]);
        atomicMax(&g_entmax[b], __float_as_int(m));
    }

    // ======== Grid-wide software barrier (self-resetting) ====================
    __syncthreads();
    if (tid == 0) {
        __threadfence();                      // publish g_fg + entmax
        atomicAdd(&g_arr, 1u);
        while (atomicAdd(&g_arr, 0u) < NBLK) { }
        unsigned int t = atomicAdd(&g_dep, 1u);
        if (t == NBLK - 1) {                  // everyone has exited the spin
            atomicExch(&g_arr, 0u);
            atomicExch(&g_dep, 0u);
        }
    }
    __syncthreads();

    // ======== Phase B: bounded EDT + weights on the same tile ================
    __shared__ unsigned char sfg[EW][56];     // 52x52 fg halo (stride 56, u32 aligned)
    __shared__ unsigned char svv[TS][56];     // vertical min-d^2

    for (int t = tid; t < EW * 56; t += 256) {
        int r = t / 56, c = t - r * 56;
        unsigned char f = 0;
        if (c < EW) {
            int gi = i0 - RAD + r, gj = j0 - RAD + c;
            if (gi >= 0 && gi < HH && gj >= 0 && gj < WW)
                f = g_fg[b * HW + gi * WW + gj];
        }
        sfg[r][c] = f;
    }
    __syncthreads();

    // vertical 21-tap min via byte SIMD: term = 200 - fg*(200-d^2), carry-free
    for (int t = tid; t < TS * 13; t += 256) {
        int r = t / 13, wc = (t - r * 13) * 4;
        unsigned int v4 = 0xC8C8C8C8u;
#pragma unroll
        for (int dr = 0; dr < 21; dr++) {
            unsigned int f4 = *(const unsigned int*)&sfg[r + dr][wc];
            int d = dr - RAD;
            v4 = __vminu4(v4, 0xC8C8C8C8u - f4 * (unsigned int)(200 - d * d));
        }
        *(unsigned int*)&svv[r][wc] = v4;
    }
    __syncthreads();

    const float Hm = __int_as_float(g_entmax[b]);
    const float invHm = 1.0f / (Hm + 1e-8f);

    float a_wkl = 0.f, a_w = 0.f;
#pragma unroll
    for (int l = 0; l < 4; l++) {
        const int tx = tx0 + l;
        int d2 = 300;
#pragma unroll
        for (int dj = 0; dj < 21; dj++) {
            int dd = dj - RAD;
            d2 = min(d2, dd * dd + (int)svv[ty][tx + dj]);
        }
        if (d2 <= RAD * RAD) {
            float wd = __expf((float)d2 * (-1.0f / 50.0f));   // 2*sigma^2 = 50
            float bnd = 0.f;
            if (sfg[ty + RAD][tx + RAD]) {
                bool er = sfg[ty + RAD - 1][tx + RAD] && sfg[ty + RAD + 1][tx + RAD]
                       && sfg[ty + RAD][tx + RAD - 1] && sfg[ty + RAD][tx + RAD + 1];
                if (!er) bnd = 1.f;
            }
            float conf = 0.1f + 0.9f * (1.f - ent[l] * invHm);
            float w = wd * (1.f + bnd) * conf;
            a_wkl += w * kl[l];
            a_w   += w;
        }
    }

#pragma unroll
    for (int o = 16; o > 0; o >>= 1) {
        a_wkl += __shfl_xor_sync(0xFFFFFFFF, a_wkl, o);
        a_w   += __shfl_xor_sync(0xFFFFFFFF, a_w, o);
    }
    __shared__ float r1[8], r2[8];
    if ((tid & 31) == 0) { r1[tid >> 5] = a_wkl; r2[tid >> 5] = a_w; }
    __syncthreads();

    if (tid == 0) {
        float s1 = 0.f, s2 = 0.f;
#pragma unroll
        for (int w = 0; w < 8; w++) { s1 += r1[w]; s2 += r2[w]; }
        atomicAdd(&g_sum_wkl, (double)s1);
        atomicAdd(&g_sum_w, (double)s2);
        __threadfence();
        unsigned int t = atomicAdd(&g_done, 1u);
        if (t == NBLK - 1) {                 // last block: finalize + reset state
            double swkl = atomicAdd(&g_sum_wkl, 0.0);
            double sw   = atomicAdd(&g_sum_w, 0.0);
            out[0] = (float)(16.0 * swkl / (sw + 1e-8));
            g_sum_wkl = 0.0;
            g_sum_w = 0.0;
#pragma unroll
            for (int bb = 0; bb < BB; bb++) g_entmax[bb] = 0;
            atomicExch(&g_done, 0u);
        }
    }
}

extern "C" void kernel_launch(void* const* d_in, const int* in_sizes, int n_in,
                              void* d_out, int out_size)
{
    const float* student = (const float*)d_in[0];
    const float* teacher = (const float*)d_in[1];
    float* out = (float*)d_out;

    ofkd_fused<<<dim3(64, BB), 256>>>(student, teacher, out);
}